// round 11
// baseline (speedup 1.0000x reference)
#include <cuda_runtime.h>
#include <cuda_bf16.h>
#include <cstdint>
#include <math.h>

#define Bq 4
#define Nq 2048
#define Dq 1024
#define MTOT (Bq * Nq)   // 8192

typedef __nv_bfloat16 bf16;

// ---------------- scratch (device globals; allocation-free) ----------------
__device__ __align__(16) bf16  g_xb [(size_t)MTOT * Dq];
__device__ __align__(16) bf16  g_Wqb[(size_t)Dq * Dq];
__device__ __align__(16) bf16  g_Wkb[(size_t)Dq * Dq];
__device__ __align__(16) bf16  g_Wvb[(size_t)Dq * Dq];
__device__ __align__(16) bf16  g_Qb [(size_t)MTOT * Dq];
__device__ __align__(16) bf16  g_Kb [(size_t)MTOT * Dq];
__device__ __align__(16) bf16  g_Vt [(size_t)Bq * Dq * Nq];   // [b][d][n]
__device__ __align__(16) bf16  g_Pb [(size_t)Bq * Nq * Nq];   // exp(scores), unnormalized
__device__ __align__(16) float g_part[(size_t)MTOT * 32];     // per-(row, coltile) partial sums
__device__ __align__(16) float g_rinv[(size_t)MTOT];          // 1 / rowsum

// ---------------- helpers ----------------
__device__ __forceinline__ uint32_t smem_u32(const void* p) {
    uint32_t a;
    asm("{ .reg .u64 t; cvta.to.shared.u64 t, %1; cvt.u32.u64 %0, t; }" : "=r"(a) : "l"(p));
    return a;
}
#define CP_ASYNC16(dst, src) asm volatile("cp.async.cg.shared.global [%0], [%1], 16;" :: "r"(dst), "l"(src))
#define CP_COMMIT()          asm volatile("cp.async.commit_group;" ::: "memory")
#define CP_WAIT1()           asm volatile("cp.async.wait_group 1;" ::: "memory")

#define LDSM4(r0, r1, r2, r3, addr)                                             \
    asm volatile("ldmatrix.sync.aligned.m8n8.x4.shared.b16 {%0,%1,%2,%3}, [%4];" \
        : "=r"(r0), "=r"(r1), "=r"(r2), "=r"(r3) : "r"(addr))

#define MMA16816(d, a, b0, b1)                                                  \
    asm volatile("mma.sync.aligned.m16n8k16.row.col.f32.bf16.bf16.f32 "         \
        "{%0,%1,%2,%3}, {%4,%5,%6,%7}, {%8,%9}, {%0,%1,%2,%3};"                 \
        : "+f"((d)[0]), "+f"((d)[1]), "+f"((d)[2]), "+f"((d)[3])                \
        : "r"((a)[0]), "r"((a)[1]), "r"((a)[2]), "r"((a)[3]), "r"(b0), "r"(b1))

// ---------------------------------------------------------------------------
// NT bf16 HMMA GEMM: C[m,n] = sum_k A[m,k]*B[n,k]. CTA tile 256x128, BK=64,
// 3-stage cp.async pipeline, 8 warps (4 along M x 2 along N), warp tile
// 64x64, fp32 accum. Smem row = 128B, swizzle (ch ^ (r&7)).
// EPI 0: +bias -> bf16 C
// EPI 3: +bias -> bf16 transposed (Vt)
// EPI 1: exp(acc/32) -> bf16 P, plus per-(row,tile) partial sums -> part
// EPI 2: acc * (gamma * rinv[row]) + x -> fp32 out
// ---------------------------------------------------------------------------
#define BKq 64
#define STAGE_BYTES 49152u   // A tile 32KB + B tile 16KB

template <int EPI>
__global__ __launch_bounds__(256, 1)
void hgemm(const bf16* __restrict__ A, const bf16* __restrict__ Bm,
           int lda, int ldb, int K, long long sA, long long sB, long long sC,
           int ldc, const float* __restrict__ ep0, const float* __restrict__ ep1,
           float* __restrict__ part, const float* __restrict__ rinv,
           void* __restrict__ Cout)
{
    extern __shared__ char smem[];
    const int tid  = threadIdx.x;
    const int wid  = tid >> 5;
    const int lane = tid & 31;
    const int wm   = wid & 3;    // 4 warps along M (64 rows each)
    const int wn   = wid >> 2;   // 2 warps along N (64 cols each)
    const int z    = blockIdx.z;
    const int rowBase = blockIdx.y * 256;
    const int colBase = blockIdx.x * 128;

    const bf16* Ab = A + (long long)z * sA;
    const bf16* Bb = Bm + (long long)z * sB;
    const uint32_t sbase = smem_u32(smem);

    const int niter = K / BKq;

    // A: 256 rows x 8 chunks(16B) = 2048 chunks; B: 128 x 8 = 1024; 256 thr
#define ISSUE_STAGE(c, s) do {                                                  \
        uint32_t aOff = sbase + (uint32_t)(s) * STAGE_BYTES;                    \
        uint32_t bOff = aOff + 32768u;                                          \
        _Pragma("unroll")                                                       \
        for (int i = 0; i < 8; i++) {                                           \
            int idx = tid + i * 256;                                            \
            int r = idx >> 3, ch = idx & 7;                                     \
            uint32_t sw = (uint32_t)((ch ^ (r & 7)) << 4) + (uint32_t)r * 128u; \
            CP_ASYNC16(aOff + sw, Ab + (size_t)(rowBase + r) * lda + (c) * BKq + ch * 8); \
        }                                                                       \
        _Pragma("unroll")                                                       \
        for (int i = 0; i < 4; i++) {                                           \
            int idx = tid + i * 256;                                            \
            int r = idx >> 3, ch = idx & 7;                                     \
            uint32_t sw = (uint32_t)((ch ^ (r & 7)) << 4) + (uint32_t)r * 128u; \
            CP_ASYNC16(bOff + sw, Bb + (size_t)(colBase + r) * ldb + (c) * BKq + ch * 8); \
        }                                                                       \
        CP_COMMIT();                                                            \
    } while (0)

    float acc[4][8][4];
#pragma unroll
    for (int i = 0; i < 4; i++)
#pragma unroll
        for (int j = 0; j < 8; j++)
#pragma unroll
            for (int e = 0; e < 4; e++) acc[i][j][e] = 0.f;

    ISSUE_STAGE(0, 0);
    ISSUE_STAGE(1, 1);

    for (int c = 0; c < niter; c++) {
        CP_WAIT1();
        __syncthreads();
        if (c + 2 < niter) { ISSUE_STAGE(c + 2, (c + 2) % 3); }
        else               { CP_COMMIT(); }   // keep group count uniform

        uint32_t aBase = sbase + (uint32_t)(c % 3) * STAGE_BYTES;
        uint32_t bBase = aBase + 32768u;

#pragma unroll
        for (int kk = 0; kk < 4; kk++) {
            const int ch = kk * 2 + (lane >> 4);
            uint32_t af[4][4];
#pragma unroll
            for (int i = 0; i < 4; i++) {
                int r = wm * 64 + i * 16 + (lane & 15);
                uint32_t addr = aBase + (uint32_t)r * 128u + (uint32_t)((ch ^ (r & 7)) << 4);
                LDSM4(af[i][0], af[i][1], af[i][2], af[i][3], addr);
            }
            uint32_t bfr[4][4];
#pragma unroll
            for (int jj = 0; jj < 4; jj++) {
                int r = wn * 64 + jj * 16 + (lane & 15);
                uint32_t addr = bBase + (uint32_t)r * 128u + (uint32_t)((ch ^ (r & 7)) << 4);
                LDSM4(bfr[jj][0], bfr[jj][1], bfr[jj][2], bfr[jj][3], addr);
            }
#pragma unroll
            for (int i = 0; i < 4; i++)
#pragma unroll
                for (int j = 0; j < 8; j++)
                    MMA16816(acc[i][j], af[i], bfr[j >> 1][j & 1], bfr[j >> 1][(j & 1) + 2]);
        }
    }
#undef ISSUE_STAGE

    // ---------------- epilogue ----------------
    const float gma = (EPI == 2) ? ep1[0] : 0.f;

#pragma unroll
    for (int i = 0; i < 4; i++) {
        const int row0 = rowBase + wm * 64 + i * 16 + (lane >> 2);
        const int row1 = row0 + 8;

        if (EPI == 1) {
            // exp + bf16 store + row partial sums
            bf16* P = (bf16*)Cout + (long long)z * sC;
            float s0 = 0.f, s1 = 0.f;
#pragma unroll
            for (int j = 0; j < 8; j++) {
                const int col = colBase + wn * 64 + j * 8 + (lane & 3) * 2;
                float e0 = __expf(acc[i][j][0] * 0.03125f);
                float e1 = __expf(acc[i][j][1] * 0.03125f);
                float e2 = __expf(acc[i][j][2] * 0.03125f);
                float e3 = __expf(acc[i][j][3] * 0.03125f);
                *(__nv_bfloat162*)(P + (size_t)row0 * ldc + col) = __floats2bfloat162_rn(e0, e1);
                *(__nv_bfloat162*)(P + (size_t)row1 * ldc + col) = __floats2bfloat162_rn(e2, e3);
                s0 += e0 + e1;
                s1 += e2 + e3;
            }
            s0 += __shfl_xor_sync(0xFFFFFFFFu, s0, 1);
            s0 += __shfl_xor_sync(0xFFFFFFFFu, s0, 2);
            s1 += __shfl_xor_sync(0xFFFFFFFFu, s1, 1);
            s1 += __shfl_xor_sync(0xFFFFFFFFu, s1, 2);
            if ((lane & 3) == 0) {
                const int slot = blockIdx.x * 2 + wn;   // gridDim.x=16 -> 32 slots
                part[(((size_t)z * Nq + row0) << 5) + slot] = s0;
                part[(((size_t)z * Nq + row1) << 5) + slot] = s1;
            }
        } else if (EPI == 2) {
            float* O = (float*)Cout + (long long)z * sC;
            const float* xp = ep0 + (long long)z * sC;
            const float f0 = gma * __ldg(&rinv[(size_t)z * Nq + row0]);
            const float f1 = gma * __ldg(&rinv[(size_t)z * Nq + row1]);
#pragma unroll
            for (int j = 0; j < 8; j++) {
                const int col = colBase + wn * 64 + j * 8 + (lane & 3) * 2;
                float2 x0 = *(const float2*)(xp + (size_t)row0 * ldc + col);
                float2 x1 = *(const float2*)(xp + (size_t)row1 * ldc + col);
                float2 v0 = make_float2(acc[i][j][0] * f0 + x0.x, acc[i][j][1] * f0 + x0.y);
                float2 v1 = make_float2(acc[i][j][2] * f1 + x1.x, acc[i][j][3] * f1 + x1.y);
                *(float2*)(O + (size_t)row0 * ldc + col) = v0;
                *(float2*)(O + (size_t)row1 * ldc + col) = v1;
            }
        } else {
#pragma unroll
            for (int j = 0; j < 8; j++) {
                const int col = colBase + wn * 64 + j * 8 + (lane & 3) * 2;
                const float a0 = acc[i][j][0], a1 = acc[i][j][1];
                const float a2 = acc[i][j][2], a3 = acc[i][j][3];
                if (EPI == 0) {
                    bf16* C = (bf16*)Cout;
                    float b0 = ep0[col], b1 = ep0[col + 1];
                    __nv_bfloat162 h0 = __floats2bfloat162_rn(a0 + b0, a1 + b1);
                    __nv_bfloat162 h1 = __floats2bfloat162_rn(a2 + b0, a3 + b1);
                    *(__nv_bfloat162*)(C + (size_t)row0 * ldc + col) = h0;
                    *(__nv_bfloat162*)(C + (size_t)row1 * ldc + col) = h1;
                } else {  // EPI 3: transposed V store
                    bf16* Vt = (bf16*)Cout;
                    float b0 = ep0[col], b1 = ep0[col + 1];
                    int bz  = row0 >> 11;
                    int mm0 = row0 & 2047, mm1 = row1 & 2047;
                    size_t base0 = ((size_t)(bz << 10) + col) * Nq;
                    size_t base1 = ((size_t)(bz << 10) + col + 1) * Nq;
                    Vt[base0 + mm0] = __float2bfloat16(a0 + b0);
                    Vt[base1 + mm0] = __float2bfloat16(a1 + b1);
                    Vt[base0 + mm1] = __float2bfloat16(a2 + b0);
                    Vt[base1 + mm1] = __float2bfloat16(a3 + b1);
                }
            }
        }
    }
}

// ---------------------------------------------------------------------------
__global__ __launch_bounds__(256)
void cvt_f32_bf16(const float* __restrict__ in, bf16* __restrict__ out, int n4)
{
    int i = blockIdx.x * blockDim.x + threadIdx.x;
    if (i < n4) {
        float4 v = reinterpret_cast<const float4*>(in)[i];
        __nv_bfloat162 a = __floats2bfloat162_rn(v.x, v.y);
        __nv_bfloat162 b = __floats2bfloat162_rn(v.z, v.w);
        uint2 u;
        u.x = *(uint32_t*)&a;
        u.y = *(uint32_t*)&b;
        reinterpret_cast<uint2*>(out)[i] = u;
    }
}

// fused conversion for the 3 weight matrices (blockIdx.y selects tensor)
__global__ __launch_bounds__(256)
void cvt_w3(const float* __restrict__ w0, const float* __restrict__ w1,
            const float* __restrict__ w2,
            bf16* __restrict__ o0, bf16* __restrict__ o1, bf16* __restrict__ o2)
{
    const float* in  = (blockIdx.y == 0) ? w0 : (blockIdx.y == 1) ? w1 : w2;
    bf16*        out = (blockIdx.y == 0) ? o0 : (blockIdx.y == 1) ? o1 : o2;
    int i = blockIdx.x * blockDim.x + threadIdx.x;
    float4 v = reinterpret_cast<const float4*>(in)[i];
    __nv_bfloat162 a = __floats2bfloat162_rn(v.x, v.y);
    __nv_bfloat162 b = __floats2bfloat162_rn(v.z, v.w);
    uint2 u;
    u.x = *(uint32_t*)&a;
    u.y = *(uint32_t*)&b;
    reinterpret_cast<uint2*>(out)[i] = u;
}

// rowsum over 32 partials per row -> reciprocal
__global__ __launch_bounds__(256)
void rowsum_inv(const float* __restrict__ part, float* __restrict__ rinv)
{
    int r = blockIdx.x * blockDim.x + threadIdx.x;   // 0..MTOT-1
    float s = 0.f;
#pragma unroll
    for (int t = 0; t < 32; t += 4) {
        float4 v = *reinterpret_cast<const float4*>(part + ((size_t)r << 5) + t);
        s += v.x + v.y + v.z + v.w;
    }
    rinv[r] = 1.f / s;
}

// ---------------------------------------------------------------------------
extern "C" void kernel_launch(void* const* d_in, const int* in_sizes, int n_in,
                              void* d_out, int out_size)
{
    const float* x     = (const float*)d_in[0];
    const float* Wq    = (const float*)d_in[1];
    const float* bqv   = (const float*)d_in[2];
    const float* Wk    = (const float*)d_in[3];
    const float* bkv   = (const float*)d_in[4];
    const float* Wv    = (const float*)d_in[5];
    const float* bvv   = (const float*)d_in[6];
    const float* gamma = (const float*)d_in[7];
    float* out = (float*)d_out;

    bf16 *xb, *Wqb, *Wkb, *Wvb, *Qb, *Kb, *Vt, *Pb;
    float *part, *rinv;
    cudaGetSymbolAddress((void**)&xb,   g_xb);
    cudaGetSymbolAddress((void**)&Wqb,  g_Wqb);
    cudaGetSymbolAddress((void**)&Wkb,  g_Wkb);
    cudaGetSymbolAddress((void**)&Wvb,  g_Wvb);
    cudaGetSymbolAddress((void**)&Qb,   g_Qb);
    cudaGetSymbolAddress((void**)&Kb,   g_Kb);
    cudaGetSymbolAddress((void**)&Vt,   g_Vt);
    cudaGetSymbolAddress((void**)&Pb,   g_Pb);
    cudaGetSymbolAddress((void**)&part, g_part);
    cudaGetSymbolAddress((void**)&rinv, g_rinv);

    const int SMEM = 3 * 49152;   // 144 KB
    cudaFuncSetAttribute(hgemm<0>, cudaFuncAttributeMaxDynamicSharedMemorySize, SMEM);
    cudaFuncSetAttribute(hgemm<1>, cudaFuncAttributeMaxDynamicSharedMemorySize, SMEM);
    cudaFuncSetAttribute(hgemm<2>, cudaFuncAttributeMaxDynamicSharedMemorySize, SMEM);
    cudaFuncSetAttribute(hgemm<3>, cudaFuncAttributeMaxDynamicSharedMemorySize, SMEM);

    // fp32 -> bf16 conversions
    cvt_f32_bf16<<<(MTOT * Dq / 4 + 255) / 256, 256>>>(x, xb, MTOT * Dq / 4);
    dim3 gW(Dq * Dq / 4 / 256, 3);
    cvt_w3<<<gW, 256>>>(Wq, Wk, Wv, Wqb, Wkb, Wvb);

    dim3 blk(256);

    // projections: M=8192, N=1024, K=1024
    dim3 gP(Dq / 128, MTOT / 256, 1);
    hgemm<0><<<gP, blk, SMEM>>>(xb, Wqb, Dq, Dq, Dq, 0, 0, 0, Dq, bqv, nullptr, nullptr, nullptr, Qb);
    hgemm<0><<<gP, blk, SMEM>>>(xb, Wkb, Dq, Dq, Dq, 0, 0, 0, Dq, bkv, nullptr, nullptr, nullptr, Kb);
    hgemm<3><<<gP, blk, SMEM>>>(xb, Wvb, Dq, Dq, Dq, 0, 0, 0, Dq, bvv, nullptr, nullptr, nullptr, Vt);

    // P = exp(Q K^T / 32) (bf16) + row partial sums, per batch
    dim3 gS(Nq / 128, Nq / 256, Bq);
    hgemm<1><<<gS, blk, SMEM>>>(Qb, Kb, Dq, Dq, Dq,
                                (long long)Nq * Dq, (long long)Nq * Dq,
                                (long long)Nq * Nq, Nq, nullptr, nullptr, part, nullptr, Pb);

    // rinv = 1 / rowsum
    rowsum_inv<<<MTOT / 256, 256>>>(part, rinv);

    // out = (P @ Vt^T) * gamma * rinv + x
    dim3 gO(Dq / 128, Nq / 256, Bq);
    hgemm<2><<<gO, blk, SMEM>>>(Pb, Vt, Nq, Nq, Nq,
                                (long long)Nq * Nq, (long long)Dq * Nq,
                                (long long)Nq * Dq, Dq, x, gamma, nullptr, rinv, out);
}

// round 13
// speedup vs baseline: 1.0814x; 1.0814x over previous
#include <cuda_runtime.h>
#include <cuda_bf16.h>
#include <cstdint>
#include <math.h>

#define Bq 4
#define Nq 2048
#define Dq 1024
#define MTOT (Bq * Nq)   // 8192

typedef __nv_bfloat16 bf16;

// ---------------- scratch (device globals; allocation-free) ----------------
__device__ __align__(16) bf16  g_xb [(size_t)MTOT * Dq];
__device__ __align__(16) bf16  g_Wqb[(size_t)Dq * Dq];
__device__ __align__(16) bf16  g_Wkb[(size_t)Dq * Dq];
__device__ __align__(16) bf16  g_Wvb[(size_t)Dq * Dq];
__device__ __align__(16) bf16  g_Qb [(size_t)MTOT * Dq];
__device__ __align__(16) bf16  g_Kb [(size_t)MTOT * Dq];
__device__ __align__(16) bf16  g_Vt [(size_t)Bq * Dq * Nq];   // [b][d][n]
__device__ __align__(16) bf16  g_Pb [(size_t)Bq * Nq * Nq];   // exp(scores), unnormalized
__device__ __align__(16) float g_part[(size_t)MTOT * 32];     // per-(row, coltile) partial sums
__device__ __align__(16) float g_rinv[(size_t)MTOT];          // 1 / rowsum

// ---------------- helpers ----------------
__device__ __forceinline__ uint32_t smem_u32(const void* p) {
    uint32_t a;
    asm("{ .reg .u64 t; cvta.to.shared.u64 t, %1; cvt.u32.u64 %0, t; }" : "=r"(a) : "l"(p));
    return a;
}
#define CP_ASYNC16(dst, src) asm volatile("cp.async.cg.shared.global [%0], [%1], 16;" :: "r"(dst), "l"(src))
#define CP_COMMIT()          asm volatile("cp.async.commit_group;" ::: "memory")
#define CP_WAIT0()           asm volatile("cp.async.wait_group 0;" ::: "memory")

#define LDSM4(r0, r1, r2, r3, addr)                                             \
    asm volatile("ldmatrix.sync.aligned.m8n8.x4.shared.b16 {%0,%1,%2,%3}, [%4];" \
        : "=r"(r0), "=r"(r1), "=r"(r2), "=r"(r3) : "r"(addr))

#define MMA16816(d, a, b0, b1)                                                  \
    asm volatile("mma.sync.aligned.m16n8k16.row.col.f32.bf16.bf16.f32 "         \
        "{%0,%1,%2,%3}, {%4,%5,%6,%7}, {%8,%9}, {%0,%1,%2,%3};"                 \
        : "+f"((d)[0]), "+f"((d)[1]), "+f"((d)[2]), "+f"((d)[3])                \
        : "r"((a)[0]), "r"((a)[1]), "r"((a)[2]), "r"((a)[3]), "r"(b0), "r"(b1))

// ---------------------------------------------------------------------------
// NT bf16 HMMA GEMM: C[m,n] = sum_k A[m,k]*B[n,k]. CTA tile 128x128, BK=64,
// 3 smem stages. Loop order per chunk c:
//   cp.async.wait_group 0  (stages c and c+1 fully landed, per-thread)
//   __syncthreads()        (cross-thread visibility + WAR for stage c+2 slot)
//   issue stage c+2        (copies overlap this chunk's compute)
//   compute (fragments ping-pong one kk ahead; at kk=3 prefetch next chunk's
//            kk=0 from stage c+1 — legal: it is resident and visible)
// 4 warps (2x2), warp tile 64x64, fp32 accum.
// EPI 0: +bias -> bf16 C
// EPI 3: +bias -> bf16 transposed (Vt)
// EPI 1: exp(acc/32) -> bf16 P, plus per-(row,tile) partial sums -> part
// EPI 2: acc * (gamma * rinv[row]) + x -> fp32 out
// ---------------------------------------------------------------------------
#define BKq 64
#define STAGE_BYTES 32768u   // A tile 16KB + B tile 16KB

template <int EPI>
__global__ __launch_bounds__(128, 2)
void hgemm(const bf16* __restrict__ A, const bf16* __restrict__ Bm,
           int lda, int ldb, int K, long long sA, long long sB, long long sC,
           int ldc, const float* __restrict__ ep0, const float* __restrict__ ep1,
           float* __restrict__ part, const float* __restrict__ rinv,
           void* __restrict__ Cout)
{
    extern __shared__ char smem[];
    const int tid  = threadIdx.x;
    const int wid  = tid >> 5;
    const int lane = tid & 31;
    const int wm   = wid & 1;    // 2 warps along M (64 rows each)
    const int wn   = wid >> 1;   // 2 warps along N (64 cols each)
    const int z    = blockIdx.z;
    const int rowBase = blockIdx.y * 128;
    const int colBase = blockIdx.x * 128;

    const bf16* Ab = A + (long long)z * sA;
    const bf16* Bb = Bm + (long long)z * sB;
    const uint32_t sbase = smem_u32(smem);

    const int niter = K / BKq;

#define ISSUE_STAGE(c, s) do {                                                  \
        uint32_t aOff = sbase + (uint32_t)(s) * STAGE_BYTES;                    \
        uint32_t bOff = aOff + 16384u;                                          \
        _Pragma("unroll")                                                       \
        for (int i = 0; i < 8; i++) {                                           \
            int idx = tid + i * 128;                                            \
            int r = idx >> 3, ch = idx & 7;                                     \
            uint32_t sw = (uint32_t)((ch ^ (r & 7)) << 4) + (uint32_t)r * 128u; \
            CP_ASYNC16(aOff + sw, Ab + (size_t)(rowBase + r) * lda + (c) * BKq + ch * 8); \
            CP_ASYNC16(bOff + sw, Bb + (size_t)(colBase + r) * ldb + (c) * BKq + ch * 8); \
        }                                                                       \
        CP_COMMIT();                                                            \
    } while (0)

    // load both operands' fragments for k-slice kkv of the stage at aBase
#define LOAD_FRAGS(p, aBase, kkv) do {                                          \
        const int ch_ = (kkv) * 2 + (lane >> 4);                                \
        _Pragma("unroll")                                                       \
        for (int i_ = 0; i_ < 4; i_++) {                                        \
            int r_ = wm * 64 + i_ * 16 + (lane & 15);                           \
            uint32_t ad_ = (aBase) + (uint32_t)r_ * 128u                        \
                         + (uint32_t)((ch_ ^ (r_ & 7)) << 4);                   \
            LDSM4(af[p][i_][0], af[p][i_][1], af[p][i_][2], af[p][i_][3], ad_); \
        }                                                                       \
        _Pragma("unroll")                                                       \
        for (int j_ = 0; j_ < 4; j_++) {                                        \
            int r_ = wn * 64 + j_ * 16 + (lane & 15);                           \
            uint32_t ad_ = (aBase) + 16384u + (uint32_t)r_ * 128u               \
                         + (uint32_t)((ch_ ^ (r_ & 7)) << 4);                   \
            LDSM4(bfr[p][j_][0], bfr[p][j_][1], bfr[p][j_][2], bfr[p][j_][3], ad_); \
        }                                                                       \
    } while (0)

    float acc[4][8][4];
#pragma unroll
    for (int i = 0; i < 4; i++)
#pragma unroll
        for (int j = 0; j < 8; j++)
#pragma unroll
            for (int e = 0; e < 4; e++) acc[i][j][e] = 0.f;

    uint32_t af[2][4][4];    // ping-pong A fragments
    uint32_t bfr[2][4][4];   // ping-pong B fragments

    ISSUE_STAGE(0, 0);
    ISSUE_STAGE(1, 1);

    for (int c = 0; c < niter; c++) {
        CP_WAIT0();          // stages c and c+1 landed (this thread's groups)
        __syncthreads();     // cross-thread visibility; WAR for stage (c+2)%3 slot
        if (c + 2 < niter) ISSUE_STAGE(c + 2, (c + 2) % 3);   // overlap with compute

        const uint32_t curB = sbase + (uint32_t)(c % 3) * STAGE_BYTES;
        const uint32_t nxtB = sbase + (uint32_t)((c + 1) % 3) * STAGE_BYTES;

        if (c == 0) LOAD_FRAGS(0, curB, 0);                   // prime frag pipeline

#pragma unroll
        for (int kk = 0; kk < 4; kk++) {
            const int p = kk & 1;
            if (kk < 3)           { LOAD_FRAGS(p ^ 1, curB, kk + 1); }
            else if (c + 1 < niter) { LOAD_FRAGS(p ^ 1, nxtB, 0); }  // next chunk's kk=0
#pragma unroll
            for (int i = 0; i < 4; i++)
#pragma unroll
                for (int j = 0; j < 8; j++)
                    MMA16816(acc[i][j], af[p][i],
                             bfr[p][j >> 1][j & 1], bfr[p][j >> 1][(j & 1) + 2]);
        }
    }
#undef ISSUE_STAGE
#undef LOAD_FRAGS

    // ---------------- epilogue ----------------
    const float gma = (EPI == 2) ? ep1[0] : 0.f;

#pragma unroll
    for (int i = 0; i < 4; i++) {
        const int row0 = rowBase + wm * 64 + i * 16 + (lane >> 2);
        const int row1 = row0 + 8;

        if (EPI == 1) {
            // exp + bf16 store + row partial sums
            bf16* P = (bf16*)Cout + (long long)z * sC;
            float s0 = 0.f, s1 = 0.f;
#pragma unroll
            for (int j = 0; j < 8; j++) {
                const int col = colBase + wn * 64 + j * 8 + (lane & 3) * 2;
                float e0 = __expf(acc[i][j][0] * 0.03125f);
                float e1 = __expf(acc[i][j][1] * 0.03125f);
                float e2 = __expf(acc[i][j][2] * 0.03125f);
                float e3 = __expf(acc[i][j][3] * 0.03125f);
                *(__nv_bfloat162*)(P + (size_t)row0 * ldc + col) = __floats2bfloat162_rn(e0, e1);
                *(__nv_bfloat162*)(P + (size_t)row1 * ldc + col) = __floats2bfloat162_rn(e2, e3);
                s0 += e0 + e1;
                s1 += e2 + e3;
            }
            s0 += __shfl_xor_sync(0xFFFFFFFFu, s0, 1);
            s0 += __shfl_xor_sync(0xFFFFFFFFu, s0, 2);
            s1 += __shfl_xor_sync(0xFFFFFFFFu, s1, 1);
            s1 += __shfl_xor_sync(0xFFFFFFFFu, s1, 2);
            if ((lane & 3) == 0) {
                const int slot = blockIdx.x * 2 + wn;      // gridDim.x=16 -> 32 slots
                part[(((size_t)z * Nq + row0) << 5) + slot] = s0;
                part[(((size_t)z * Nq + row1) << 5) + slot] = s1;
            }
        } else if (EPI == 2) {
            float* O = (float*)Cout + (long long)z * sC;
            const float* xp = ep0 + (long long)z * sC;
            const float f0 = gma * __ldg(&rinv[(size_t)z * Nq + row0]);
            const float f1 = gma * __ldg(&rinv[(size_t)z * Nq + row1]);
#pragma unroll
            for (int j = 0; j < 8; j++) {
                const int col = colBase + wn * 64 + j * 8 + (lane & 3) * 2;
                float2 x0 = *(const float2*)(xp + (size_t)row0 * ldc + col);
                float2 x1 = *(const float2*)(xp + (size_t)row1 * ldc + col);
                float2 v0 = make_float2(acc[i][j][0] * f0 + x0.x, acc[i][j][1] * f0 + x0.y);
                float2 v1 = make_float2(acc[i][j][2] * f1 + x1.x, acc[i][j][3] * f1 + x1.y);
                *(float2*)(O + (size_t)row0 * ldc + col) = v0;
                *(float2*)(O + (size_t)row1 * ldc + col) = v1;
            }
        } else {
#pragma unroll
            for (int j = 0; j < 8; j++) {
                const int col = colBase + wn * 64 + j * 8 + (lane & 3) * 2;
                const float a0 = acc[i][j][0], a1 = acc[i][j][1];
                const float a2 = acc[i][j][2], a3 = acc[i][j][3];
                if (EPI == 0) {
                    bf16* C = (bf16*)Cout;
                    float b0 = ep0[col], b1 = ep0[col + 1];
                    __nv_bfloat162 h0 = __floats2bfloat162_rn(a0 + b0, a1 + b1);
                    __nv_bfloat162 h1 = __floats2bfloat162_rn(a2 + b0, a3 + b1);
                    *(__nv_bfloat162*)(C + (size_t)row0 * ldc + col) = h0;
                    *(__nv_bfloat162*)(C + (size_t)row1 * ldc + col) = h1;
                } else {  // EPI 3: transposed V store
                    bf16* Vt = (bf16*)Cout;
                    float b0 = ep0[col], b1 = ep0[col + 1];
                    int bz  = row0 >> 11;
                    int mm0 = row0 & 2047, mm1 = row1 & 2047;
                    size_t base0 = ((size_t)(bz << 10) + col) * Nq;
                    size_t base1 = ((size_t)(bz << 10) + col + 1) * Nq;
                    Vt[base0 + mm0] = __float2bfloat16(a0 + b0);
                    Vt[base1 + mm0] = __float2bfloat16(a1 + b1);
                    Vt[base0 + mm1] = __float2bfloat16(a2 + b0);
                    Vt[base1 + mm1] = __float2bfloat16(a3 + b1);
                }
            }
        }
    }
}

// ---------------------------------------------------------------------------
__global__ __launch_bounds__(256)
void cvt_f32_bf16(const float* __restrict__ in, bf16* __restrict__ out, int n4)
{
    int i = blockIdx.x * blockDim.x + threadIdx.x;
    if (i < n4) {
        float4 v = reinterpret_cast<const float4*>(in)[i];
        __nv_bfloat162 a = __floats2bfloat162_rn(v.x, v.y);
        __nv_bfloat162 b = __floats2bfloat162_rn(v.z, v.w);
        uint2 u;
        u.x = *(uint32_t*)&a;
        u.y = *(uint32_t*)&b;
        reinterpret_cast<uint2*>(out)[i] = u;
    }
}

// fused conversion for the 3 weight matrices (blockIdx.y selects tensor)
__global__ __launch_bounds__(256)
void cvt_w3(const float* __restrict__ w0, const float* __restrict__ w1,
            const float* __restrict__ w2,
            bf16* __restrict__ o0, bf16* __restrict__ o1, bf16* __restrict__ o2)
{
    const float* in  = (blockIdx.y == 0) ? w0 : (blockIdx.y == 1) ? w1 : w2;
    bf16*        out = (blockIdx.y == 0) ? o0 : (blockIdx.y == 1) ? o1 : o2;
    int i = blockIdx.x * blockDim.x + threadIdx.x;
    float4 v = reinterpret_cast<const float4*>(in)[i];
    __nv_bfloat162 a = __floats2bfloat162_rn(v.x, v.y);
    __nv_bfloat162 b = __floats2bfloat162_rn(v.z, v.w);
    uint2 u;
    u.x = *(uint32_t*)&a;
    u.y = *(uint32_t*)&b;
    reinterpret_cast<uint2*>(out)[i] = u;
}

// rowsum over 32 partials per row -> reciprocal
__global__ __launch_bounds__(256)
void rowsum_inv(const float* __restrict__ part, float* __restrict__ rinv)
{
    int r = blockIdx.x * blockDim.x + threadIdx.x;   // 0..MTOT-1
    float s = 0.f;
#pragma unroll
    for (int t = 0; t < 32; t += 4) {
        float4 v = *reinterpret_cast<const float4*>(part + ((size_t)r << 5) + t);
        s += v.x + v.y + v.z + v.w;
    }
    rinv[r] = 1.f / s;
}

// ---------------------------------------------------------------------------
extern "C" void kernel_launch(void* const* d_in, const int* in_sizes, int n_in,
                              void* d_out, int out_size)
{
    const float* x     = (const float*)d_in[0];
    const float* Wq    = (const float*)d_in[1];
    const float* bqv   = (const float*)d_in[2];
    const float* Wk    = (const float*)d_in[3];
    const float* bkv   = (const float*)d_in[4];
    const float* Wv    = (const float*)d_in[5];
    const float* bvv   = (const float*)d_in[6];
    const float* gamma = (const float*)d_in[7];
    float* out = (float*)d_out;

    bf16 *xb, *Wqb, *Wkb, *Wvb, *Qb, *Kb, *Vt, *Pb;
    float *part, *rinv;
    cudaGetSymbolAddress((void**)&xb,   g_xb);
    cudaGetSymbolAddress((void**)&Wqb,  g_Wqb);
    cudaGetSymbolAddress((void**)&Wkb,  g_Wkb);
    cudaGetSymbolAddress((void**)&Wvb,  g_Wvb);
    cudaGetSymbolAddress((void**)&Qb,   g_Qb);
    cudaGetSymbolAddress((void**)&Kb,   g_Kb);
    cudaGetSymbolAddress((void**)&Vt,   g_Vt);
    cudaGetSymbolAddress((void**)&Pb,   g_Pb);
    cudaGetSymbolAddress((void**)&part, g_part);
    cudaGetSymbolAddress((void**)&rinv, g_rinv);

    const int SMEM = 96 * 1024;
    cudaFuncSetAttribute(hgemm<0>, cudaFuncAttributeMaxDynamicSharedMemorySize, SMEM);
    cudaFuncSetAttribute(hgemm<1>, cudaFuncAttributeMaxDynamicSharedMemorySize, SMEM);
    cudaFuncSetAttribute(hgemm<2>, cudaFuncAttributeMaxDynamicSharedMemorySize, SMEM);
    cudaFuncSetAttribute(hgemm<3>, cudaFuncAttributeMaxDynamicSharedMemorySize, SMEM);

    // fp32 -> bf16 conversions
    cvt_f32_bf16<<<(MTOT * Dq / 4 + 255) / 256, 256>>>(x, xb, MTOT * Dq / 4);
    dim3 gW(Dq * Dq / 4 / 256, 3);
    cvt_w3<<<gW, 256>>>(Wq, Wk, Wv, Wqb, Wkb, Wvb);

    dim3 blk(128);

    // projections: M=8192, N=1024, K=1024
    dim3 gP(Dq / 128, MTOT / 128, 1);
    hgemm<0><<<gP, blk, SMEM>>>(xb, Wqb, Dq, Dq, Dq, 0, 0, 0, Dq, bqv, nullptr, nullptr, nullptr, Qb);
    hgemm<0><<<gP, blk, SMEM>>>(xb, Wkb, Dq, Dq, Dq, 0, 0, 0, Dq, bkv, nullptr, nullptr, nullptr, Kb);
    hgemm<3><<<gP, blk, SMEM>>>(xb, Wvb, Dq, Dq, Dq, 0, 0, 0, Dq, bvv, nullptr, nullptr, nullptr, Vt);

    // P = exp(Q K^T / 32) (bf16) + row partial sums, per batch
    dim3 gS(Nq / 128, Nq / 128, Bq);
    hgemm<1><<<gS, blk, SMEM>>>(Qb, Kb, Dq, Dq, Dq,
                                (long long)Nq * Dq, (long long)Nq * Dq,
                                (long long)Nq * Nq, Nq, nullptr, nullptr, part, nullptr, Pb);

    // rinv = 1 / rowsum
    rowsum_inv<<<MTOT / 256, 256>>>(part, rinv);

    // out = (P @ Vt^T) * gamma * rinv + x
    dim3 gO(Dq / 128, Nq / 128, Bq);
    hgemm<2><<<gO, blk, SMEM>>>(Pb, Vt, Nq, Nq, Nq,
                                (long long)Nq * Nq, (long long)Dq * Nq,
                                (long long)Nq * Dq, Dq, x, gamma, nullptr, rinv, out);
}

// round 14
// speedup vs baseline: 1.1909x; 1.1013x over previous
#include <cuda_runtime.h>
#include <cuda_bf16.h>
#include <cstdint>
#include <math.h>

#define Bq 4
#define Nq 2048
#define Dq 1024
#define MTOT (Bq * Nq)   // 8192

typedef __nv_bfloat16 bf16;

// ---------------- scratch (device globals; allocation-free) ----------------
__device__ __align__(16) bf16  g_xb [(size_t)MTOT * Dq];
__device__ __align__(16) bf16  g_Wqb[(size_t)Dq * Dq];
__device__ __align__(16) bf16  g_Wkb[(size_t)Dq * Dq];
__device__ __align__(16) bf16  g_Wvb[(size_t)Dq * Dq];
__device__ __align__(16) bf16  g_Qb [(size_t)MTOT * Dq];
__device__ __align__(16) bf16  g_Kb [(size_t)MTOT * Dq];
__device__ __align__(16) bf16  g_Vt [(size_t)Bq * Dq * Nq];   // [b][d][n]
__device__ __align__(16) bf16  g_Pb [(size_t)Bq * Nq * Nq];   // exp(scores), unnormalized
__device__ __align__(16) float g_part[(size_t)MTOT * 32];     // per-(row, coltile) partial sums
__device__ __align__(16) float g_rinv[(size_t)MTOT];          // 1 / rowsum

// ---------------- helpers ----------------
__device__ __forceinline__ uint32_t smem_u32(const void* p) {
    uint32_t a;
    asm("{ .reg .u64 t; cvta.to.shared.u64 t, %1; cvt.u32.u64 %0, t; }" : "=r"(a) : "l"(p));
    return a;
}
#define CP_ASYNC16(dst, src) asm volatile("cp.async.cg.shared.global [%0], [%1], 16;" :: "r"(dst), "l"(src))
#define CP_COMMIT()          asm volatile("cp.async.commit_group;" ::: "memory")
#define CP_WAIT0()           asm volatile("cp.async.wait_group 0;" ::: "memory")

#define LDSM4(r0, r1, r2, r3, addr)                                             \
    asm volatile("ldmatrix.sync.aligned.m8n8.x4.shared.b16 {%0,%1,%2,%3}, [%4];" \
        : "=r"(r0), "=r"(r1), "=r"(r2), "=r"(r3) : "r"(addr))

#define MMA16816(d, a, b0, b1)                                                  \
    asm volatile("mma.sync.aligned.m16n8k16.row.col.f32.bf16.bf16.f32 "         \
        "{%0,%1,%2,%3}, {%4,%5,%6,%7}, {%8,%9}, {%0,%1,%2,%3};"                 \
        : "+f"((d)[0]), "+f"((d)[1]), "+f"((d)[2]), "+f"((d)[3])                \
        : "r"((a)[0]), "r"((a)[1]), "r"((a)[2]), "r"((a)[3]), "r"(b0), "r"(b1))

// ---------------------------------------------------------------------------
// NT bf16 HMMA GEMM: C[m,n] = sum_k A[m,k]*B[n,k]. CTA tile 128x128, BK=64,
// 3 smem stages. Per chunk: wait_group 0 -> syncthreads -> issue c+2 ->
// compute with ping-pong fragments one kk ahead (kk=3 prefetches next chunk's
// kk=0 from the resident c+1 stage). 4 warps (2x2), warp tile 64x64.
// EPI 0: +bias -> bf16 C
// EPI 3: +bias -> bf16 transposed (Vt)
// EPI 1: exp(acc/32) -> bf16 P, plus per-(row,tile) partial sums -> part
// EPI 2: acc * (gamma * rinv[row]) + x -> fp32 out
// ---------------------------------------------------------------------------
#define BKq 64
#define STAGE_BYTES 32768u   // A tile 16KB + B tile 16KB

template <int EPI>
__global__ __launch_bounds__(128, 2)
void hgemm(const bf16* __restrict__ A, const bf16* __restrict__ Bm,
           int lda, int ldb, int K, long long sA, long long sB, long long sC,
           int ldc, const float* __restrict__ ep0, const float* __restrict__ ep1,
           float* __restrict__ part, const float* __restrict__ rinv,
           void* __restrict__ Cout)
{
    extern __shared__ char smem[];
    const int tid  = threadIdx.x;
    const int wid  = tid >> 5;
    const int lane = tid & 31;
    const int wm   = wid & 1;    // 2 warps along M (64 rows each)
    const int wn   = wid >> 1;   // 2 warps along N (64 cols each)
    const int z    = blockIdx.z;
    const int rowBase = blockIdx.y * 128;
    const int colBase = blockIdx.x * 128;

    const bf16* Ab = A + (long long)z * sA;
    const bf16* Bb = Bm + (long long)z * sB;
    const uint32_t sbase = smem_u32(smem);

    const int niter = K / BKq;

#define ISSUE_STAGE(c, s) do {                                                  \
        uint32_t aOff = sbase + (uint32_t)(s) * STAGE_BYTES;                    \
        uint32_t bOff = aOff + 16384u;                                          \
        _Pragma("unroll")                                                       \
        for (int i = 0; i < 8; i++) {                                           \
            int idx = tid + i * 128;                                            \
            int r = idx >> 3, ch = idx & 7;                                     \
            uint32_t sw = (uint32_t)((ch ^ (r & 7)) << 4) + (uint32_t)r * 128u; \
            CP_ASYNC16(aOff + sw, Ab + (size_t)(rowBase + r) * lda + (c) * BKq + ch * 8); \
            CP_ASYNC16(bOff + sw, Bb + (size_t)(colBase + r) * ldb + (c) * BKq + ch * 8); \
        }                                                                       \
        CP_COMMIT();                                                            \
    } while (0)

    // load both operands' fragments for k-slice kkv of the stage at aBase
#define LOAD_FRAGS(p, aBase, kkv) do {                                          \
        const int ch_ = (kkv) * 2 + (lane >> 4);                                \
        _Pragma("unroll")                                                       \
        for (int i_ = 0; i_ < 4; i_++) {                                        \
            int r_ = wm * 64 + i_ * 16 + (lane & 15);                           \
            uint32_t ad_ = (aBase) + (uint32_t)r_ * 128u                        \
                         + (uint32_t)((ch_ ^ (r_ & 7)) << 4);                   \
            LDSM4(af[p][i_][0], af[p][i_][1], af[p][i_][2], af[p][i_][3], ad_); \
        }                                                                       \
        _Pragma("unroll")                                                       \
        for (int j_ = 0; j_ < 4; j_++) {                                        \
            int r_ = wn * 64 + j_ * 16 + (lane & 15);                           \
            uint32_t ad_ = (aBase) + 16384u + (uint32_t)r_ * 128u               \
                         + (uint32_t)((ch_ ^ (r_ & 7)) << 4);                   \
            LDSM4(bfr[p][j_][0], bfr[p][j_][1], bfr[p][j_][2], bfr[p][j_][3], ad_); \
        }                                                                       \
    } while (0)

    float acc[4][8][4];
#pragma unroll
    for (int i = 0; i < 4; i++)
#pragma unroll
        for (int j = 0; j < 8; j++)
#pragma unroll
            for (int e = 0; e < 4; e++) acc[i][j][e] = 0.f;

    uint32_t af[2][4][4];    // ping-pong A fragments
    uint32_t bfr[2][4][4];   // ping-pong B fragments

    ISSUE_STAGE(0, 0);
    ISSUE_STAGE(1, 1);

    for (int c = 0; c < niter; c++) {
        CP_WAIT0();          // stages c and c+1 landed (this thread's groups)
        __syncthreads();     // cross-thread visibility; WAR for stage (c+2)%3 slot
        if (c + 2 < niter) ISSUE_STAGE(c + 2, (c + 2) % 3);   // overlap with compute

        const uint32_t curB = sbase + (uint32_t)(c % 3) * STAGE_BYTES;
        const uint32_t nxtB = sbase + (uint32_t)((c + 1) % 3) * STAGE_BYTES;

        if (c == 0) LOAD_FRAGS(0, curB, 0);                   // prime frag pipeline

#pragma unroll
        for (int kk = 0; kk < 4; kk++) {
            const int p = kk & 1;
            if (kk < 3)           { LOAD_FRAGS(p ^ 1, curB, kk + 1); }
            else if (c + 1 < niter) { LOAD_FRAGS(p ^ 1, nxtB, 0); }  // next chunk's kk=0
#pragma unroll
            for (int i = 0; i < 4; i++)
#pragma unroll
                for (int j = 0; j < 8; j++)
                    MMA16816(acc[i][j], af[p][i],
                             bfr[p][j >> 1][j & 1], bfr[p][j >> 1][(j & 1) + 2]);
        }
    }
#undef ISSUE_STAGE
#undef LOAD_FRAGS

    // ---------------- epilogue ----------------
    const float gma = (EPI == 2) ? ep1[0] : 0.f;

#pragma unroll
    for (int i = 0; i < 4; i++) {
        const int row0 = rowBase + wm * 64 + i * 16 + (lane >> 2);
        const int row1 = row0 + 8;

        if (EPI == 1) {
            // exp + bf16 store + row partial sums
            bf16* P = (bf16*)Cout + (long long)z * sC;
            float s0 = 0.f, s1 = 0.f;
#pragma unroll
            for (int j = 0; j < 8; j++) {
                const int col = colBase + wn * 64 + j * 8 + (lane & 3) * 2;
                float e0 = __expf(acc[i][j][0] * 0.03125f);
                float e1 = __expf(acc[i][j][1] * 0.03125f);
                float e2 = __expf(acc[i][j][2] * 0.03125f);
                float e3 = __expf(acc[i][j][3] * 0.03125f);
                *(__nv_bfloat162*)(P + (size_t)row0 * ldc + col) = __floats2bfloat162_rn(e0, e1);
                *(__nv_bfloat162*)(P + (size_t)row1 * ldc + col) = __floats2bfloat162_rn(e2, e3);
                s0 += e0 + e1;
                s1 += e2 + e3;
            }
            s0 += __shfl_xor_sync(0xFFFFFFFFu, s0, 1);
            s0 += __shfl_xor_sync(0xFFFFFFFFu, s0, 2);
            s1 += __shfl_xor_sync(0xFFFFFFFFu, s1, 1);
            s1 += __shfl_xor_sync(0xFFFFFFFFu, s1, 2);
            if ((lane & 3) == 0) {
                const int slot = blockIdx.x * 2 + wn;      // gridDim.x=16 -> 32 slots
                part[(((size_t)z * Nq + row0) << 5) + slot] = s0;
                part[(((size_t)z * Nq + row1) << 5) + slot] = s1;
            }
        } else if (EPI == 2) {
            float* O = (float*)Cout + (long long)z * sC;
            const float* xp = ep0 + (long long)z * sC;
            const float f0 = gma * __ldg(&rinv[(size_t)z * Nq + row0]);
            const float f1 = gma * __ldg(&rinv[(size_t)z * Nq + row1]);
#pragma unroll
            for (int j = 0; j < 8; j++) {
                const int col = colBase + wn * 64 + j * 8 + (lane & 3) * 2;
                float2 x0 = *(const float2*)(xp + (size_t)row0 * ldc + col);
                float2 x1 = *(const float2*)(xp + (size_t)row1 * ldc + col);
                float2 v0 = make_float2(acc[i][j][0] * f0 + x0.x, acc[i][j][1] * f0 + x0.y);
                float2 v1 = make_float2(acc[i][j][2] * f1 + x1.x, acc[i][j][3] * f1 + x1.y);
                *(float2*)(O + (size_t)row0 * ldc + col) = v0;
                *(float2*)(O + (size_t)row1 * ldc + col) = v1;
            }
        } else {
#pragma unroll
            for (int j = 0; j < 8; j++) {
                const int col = colBase + wn * 64 + j * 8 + (lane & 3) * 2;
                const float a0 = acc[i][j][0], a1 = acc[i][j][1];
                const float a2 = acc[i][j][2], a3 = acc[i][j][3];
                if (EPI == 0) {
                    bf16* C = (bf16*)Cout;
                    float b0 = ep0[col], b1 = ep0[col + 1];
                    __nv_bfloat162 h0 = __floats2bfloat162_rn(a0 + b0, a1 + b1);
                    __nv_bfloat162 h1 = __floats2bfloat162_rn(a2 + b0, a3 + b1);
                    *(__nv_bfloat162*)(C + (size_t)row0 * ldc + col) = h0;
                    *(__nv_bfloat162*)(C + (size_t)row1 * ldc + col) = h1;
                } else {  // EPI 3: transposed V store
                    bf16* Vt = (bf16*)Cout;
                    float b0 = ep0[col], b1 = ep0[col + 1];
                    int bz  = row0 >> 11;
                    int mm0 = row0 & 2047, mm1 = row1 & 2047;
                    size_t base0 = ((size_t)(bz << 10) + col) * Nq;
                    size_t base1 = ((size_t)(bz << 10) + col + 1) * Nq;
                    Vt[base0 + mm0] = __float2bfloat16(a0 + b0);
                    Vt[base1 + mm0] = __float2bfloat16(a1 + b1);
                    Vt[base0 + mm1] = __float2bfloat16(a2 + b0);
                    Vt[base1 + mm1] = __float2bfloat16(a3 + b1);
                }
            }
        }
    }
}

// ---------------------------------------------------------------------------
__global__ __launch_bounds__(256)
void cvt_f32_bf16(const float* __restrict__ in, bf16* __restrict__ out, int n4)
{
    int i = blockIdx.x * blockDim.x + threadIdx.x;
    if (i < n4) {
        float4 v = reinterpret_cast<const float4*>(in)[i];
        __nv_bfloat162 a = __floats2bfloat162_rn(v.x, v.y);
        __nv_bfloat162 b = __floats2bfloat162_rn(v.z, v.w);
        uint2 u;
        u.x = *(uint32_t*)&a;
        u.y = *(uint32_t*)&b;
        reinterpret_cast<uint2*>(out)[i] = u;
    }
}

// fused conversion for the 3 weight matrices (blockIdx.y selects tensor)
__global__ __launch_bounds__(256)
void cvt_w3(const float* __restrict__ w0, const float* __restrict__ w1,
            const float* __restrict__ w2,
            bf16* __restrict__ o0, bf16* __restrict__ o1, bf16* __restrict__ o2)
{
    const float* in  = (blockIdx.y == 0) ? w0 : (blockIdx.y == 1) ? w1 : w2;
    bf16*        out = (blockIdx.y == 0) ? o0 : (blockIdx.y == 1) ? o1 : o2;
    int i = blockIdx.x * blockDim.x + threadIdx.x;
    float4 v = reinterpret_cast<const float4*>(in)[i];
    __nv_bfloat162 a = __floats2bfloat162_rn(v.x, v.y);
    __nv_bfloat162 b = __floats2bfloat162_rn(v.z, v.w);
    uint2 u;
    u.x = *(uint32_t*)&a;
    u.y = *(uint32_t*)&b;
    reinterpret_cast<uint2*>(out)[i] = u;
}

// rowsum over 32 partials per row -> reciprocal
__global__ __launch_bounds__(256)
void rowsum_inv(const float* __restrict__ part, float* __restrict__ rinv)
{
    int r = blockIdx.x * blockDim.x + threadIdx.x;   // 0..MTOT-1
    float s = 0.f;
#pragma unroll
    for (int t = 0; t < 32; t += 4) {
        float4 v = *reinterpret_cast<const float4*>(part + ((size_t)r << 5) + t);
        s += v.x + v.y + v.z + v.w;
    }
    rinv[r] = 1.f / s;
}

// ---------------------------------------------------------------------------
// Graph fork-join: K-proj and V-proj run on side streams so V-proj overlaps
// the scores GEMM (it is only needed by PV) and Q/K/V wave tails fill each
// other. Streams/events are host handles, created once (no device alloc).
// ---------------------------------------------------------------------------
extern "C" void kernel_launch(void* const* d_in, const int* in_sizes, int n_in,
                              void* d_out, int out_size)
{
    const float* x     = (const float*)d_in[0];
    const float* Wq    = (const float*)d_in[1];
    const float* bqv   = (const float*)d_in[2];
    const float* Wk    = (const float*)d_in[3];
    const float* bkv   = (const float*)d_in[4];
    const float* Wv    = (const float*)d_in[5];
    const float* bvv   = (const float*)d_in[6];
    const float* gamma = (const float*)d_in[7];
    float* out = (float*)d_out;

    bf16 *xb, *Wqb, *Wkb, *Wvb, *Qb, *Kb, *Vt, *Pb;
    float *part, *rinv;
    cudaGetSymbolAddress((void**)&xb,   g_xb);
    cudaGetSymbolAddress((void**)&Wqb,  g_Wqb);
    cudaGetSymbolAddress((void**)&Wkb,  g_Wkb);
    cudaGetSymbolAddress((void**)&Wvb,  g_Wvb);
    cudaGetSymbolAddress((void**)&Qb,   g_Qb);
    cudaGetSymbolAddress((void**)&Kb,   g_Kb);
    cudaGetSymbolAddress((void**)&Vt,   g_Vt);
    cudaGetSymbolAddress((void**)&Pb,   g_Pb);
    cudaGetSymbolAddress((void**)&part, g_part);
    cudaGetSymbolAddress((void**)&rinv, g_rinv);

    const int SMEM = 96 * 1024;

    static cudaStream_t sK = nullptr, sV = nullptr;
    static cudaEvent_t evFork = nullptr, evK = nullptr, evV = nullptr;
    if (sK == nullptr) {
        cudaStreamCreateWithFlags(&sK, cudaStreamNonBlocking);
        cudaStreamCreateWithFlags(&sV, cudaStreamNonBlocking);
        cudaEventCreateWithFlags(&evFork, cudaEventDisableTiming);
        cudaEventCreateWithFlags(&evK,    cudaEventDisableTiming);
        cudaEventCreateWithFlags(&evV,    cudaEventDisableTiming);
        cudaFuncSetAttribute(hgemm<0>, cudaFuncAttributeMaxDynamicSharedMemorySize, SMEM);
        cudaFuncSetAttribute(hgemm<1>, cudaFuncAttributeMaxDynamicSharedMemorySize, SMEM);
        cudaFuncSetAttribute(hgemm<2>, cudaFuncAttributeMaxDynamicSharedMemorySize, SMEM);
        cudaFuncSetAttribute(hgemm<3>, cudaFuncAttributeMaxDynamicSharedMemorySize, SMEM);
    }

    dim3 blk(128);
    dim3 gP(Dq / 128, MTOT / 128, 1);
    dim3 gS(Nq / 128, Nq / 128, Bq);
    dim3 gO(Dq / 128, Nq / 128, Bq);
    dim3 gW(Dq * Dq / 4 / 256, 3);

    // trunk: conversions (inputs to all projections)
    cvt_f32_bf16<<<(MTOT * Dq / 4 + 255) / 256, 256>>>(x, xb, MTOT * Dq / 4);
    cvt_w3<<<gW, 256>>>(Wq, Wk, Wv, Wqb, Wkb, Wvb);

    // fork
    cudaEventRecord(evFork, 0);
    cudaStreamWaitEvent(sK, evFork, 0);
    cudaStreamWaitEvent(sV, evFork, 0);

    // Q on trunk, K and V on side streams
    hgemm<0><<<gP, blk, SMEM, 0 >>>(xb, Wqb, Dq, Dq, Dq, 0, 0, 0, Dq, bqv, nullptr, nullptr, nullptr, Qb);
    hgemm<0><<<gP, blk, SMEM, sK>>>(xb, Wkb, Dq, Dq, Dq, 0, 0, 0, Dq, bkv, nullptr, nullptr, nullptr, Kb);
    hgemm<3><<<gP, blk, SMEM, sV>>>(xb, Wvb, Dq, Dq, Dq, 0, 0, 0, Dq, bvv, nullptr, nullptr, nullptr, Vt);
    cudaEventRecord(evK, sK);
    cudaEventRecord(evV, sV);

    // scores needs Q (trunk order) + K (event); V-proj keeps running alongside
    cudaStreamWaitEvent(0, evK, 0);
    hgemm<1><<<gS, blk, SMEM>>>(Qb, Kb, Dq, Dq, Dq,
                                (long long)Nq * Dq, (long long)Nq * Dq,
                                (long long)Nq * Nq, Nq, nullptr, nullptr, part, nullptr, Pb);

    rowsum_inv<<<MTOT / 256, 256>>>(part, rinv);

    // PV needs V (event) + P + rinv (trunk order)
    cudaStreamWaitEvent(0, evV, 0);
    hgemm<2><<<gO, blk, SMEM>>>(Pb, Vt, Nq, Nq, Nq,
                                (long long)Nq * Nq, (long long)Dq * Nq,
                                (long long)Nq * Dq, Dq, x, gamma, nullptr, rinv, out);
}